// round 13
// baseline (speedup 1.0000x reference)
#include <cuda_runtime.h>
#include <cstdint>

#define ROWS 4096
#define COLS 8192
#define KK   8
#define TH   2.75f
#define NCAND 4   // per-lane candidate slots

// ---------- packed key helpers ----------

// Order-preserving float->uint map, packed with ~idx so that a single u64
// ">" gives (value desc, index asc) ordering.
__device__ __forceinline__ unsigned long long pack_key(float v, int idx) {
    unsigned u = __float_as_uint(v);
    unsigned fk = (u & 0x80000000u) ? ~u : (u | 0x80000000u);
    return ((unsigned long long)fk << 32) | (unsigned)(~(unsigned)idx);
}

__device__ __forceinline__ void unpack_key(unsigned long long k, float& v, int& idx) {
    unsigned fk = (unsigned)(k >> 32);
    unsigned u  = (fk & 0x80000000u) ? (fk ^ 0x80000000u) : ~fk;
    v   = __uint_as_float(u);
    idx = (int)(~(unsigned)(k & 0xFFFFFFFFull));
}

// ---------- exact top-8 warp machinery (proven) ----------

__device__ __forceinline__ void cmpswap(unsigned long long& a, unsigned long long& b) {
    unsigned long long lo = a < b ? a : b;
    a = a > b ? a : b;
    b = lo;
}

__device__ __forceinline__ void bitonic_clean8(unsigned long long (&k)[KK]) {
    cmpswap(k[0], k[4]); cmpswap(k[1], k[5]); cmpswap(k[2], k[6]); cmpswap(k[3], k[7]);
    cmpswap(k[0], k[2]); cmpswap(k[1], k[3]); cmpswap(k[4], k[6]); cmpswap(k[5], k[7]);
    cmpswap(k[0], k[1]); cmpswap(k[2], k[3]); cmpswap(k[4], k[5]); cmpswap(k[6], k[7]);
}

__device__ __forceinline__ void warp_merge_step(unsigned long long (&k)[KK], int d) {
    unsigned long long o[KK];
    #pragma unroll
    for (int i = 0; i < KK; i++)
        o[i] = __shfl_xor_sync(0xffffffffu, k[KK - 1 - i], d);
    #pragma unroll
    for (int i = 0; i < KK; i++)
        k[i] = k[i] > o[i] ? k[i] : o[i];
    bitonic_clean8(k);
}

__device__ __forceinline__ void insert8(unsigned long long (&k)[KK], unsigned long long c) {
    if (c > k[KK - 1]) {
        k[KK - 1] = c;
        #pragma unroll
        for (int j = KK - 1; j > 0; --j) {
            if (k[j] > k[j - 1]) { unsigned long long t = k[j]; k[j] = k[j - 1]; k[j - 1] = t; }
        }
    }
}

// Insert into 4-slot sorted-descending per-lane candidate list; count all hits.
__device__ __forceinline__ void insert_cand(unsigned long long (&c)[NCAND], int& cnt,
                                            float f, int idx) {
    cnt++;
    unsigned long long k = pack_key(f, idx);
    if (k > c[NCAND - 1]) {
        c[NCAND - 1] = k;
        #pragma unroll
        for (int j = NCAND - 1; j > 0; --j) {
            if (c[j] > c[j - 1]) { unsigned long long t = c[j]; c[j] = c[j - 1]; c[j - 1] = t; }
        }
    }
}

// IDX_MODE: 1 = indices as float32 at element offset ROWS*KK (confirmed layout)
//           0 = indices as int64 at byte offset ROWS*KK*4 (fallback)
template <int IDX_MODE>
__device__ __forceinline__ void write_row_out(void* d_out, int row,
                                              const unsigned long long (&k)[KK]) {
    float* out_v = (float*)d_out;
    #pragma unroll
    for (int i = 0; i < KK; i++) {
        float val; int idx;
        unpack_key(k[i], val, idx);
        out_v[(size_t)row * KK + i] = val;
        if (IDX_MODE == 1) {
            float* out_i = out_v + (size_t)ROWS * KK;
            out_i[(size_t)row * KK + i] = (float)idx;
        } else {
            long long* out_i = (long long*)((char*)d_out + (size_t)ROWS * KK * sizeof(float));
            out_i[(size_t)row * KK + i] = (long long)idx;
        }
    }
}

// ---------- kernel: one warp per row, no barriers, single wave ----------

template <int IDX_MODE>
__global__ __launch_bounds__(32) void topk8_warp_kernel(const float* __restrict__ x,
                                                        void* __restrict__ d_out) {
    const int row  = blockIdx.x;
    const int lane = threadIdx.x;
    const float4* xr = reinterpret_cast<const float4*>(x + (size_t)row * COLS);

    unsigned long long cand[NCAND] = {0ull, 0ull, 0ull, 0ull};
    int cnt = 0;

    // 8 iterations x (8 front-batched LDG.128 per lane) = 8192 elems/row
    for (int it = 0; it < 8; it++) {
        float4 v[8];
        #pragma unroll
        for (int u = 0; u < 8; u++)
            v[u] = xr[it * 256 + u * 32 + lane];

        #pragma unroll
        for (int u = 0; u < 8; u++) {
            float m = fmaxf(fmaxf(v[u].x, v[u].y), fmaxf(v[u].z, v[u].w));
            if (m > TH) {  // rare: P ~ 1.2% per lane per u-block
                int base = (it * 256 + u * 32 + lane) * 4;
                if (v[u].x > TH) insert_cand(cand, cnt, v[u].x, base + 0);
                if (v[u].y > TH) insert_cand(cand, cnt, v[u].y, base + 1);
                if (v[u].z > TH) insert_cand(cand, cnt, v[u].z, base + 2);
                if (v[u].w > TH) insert_cand(cand, cnt, v[u].w, base + 3);
            }
        }
    }

    // Exactness guards (warp-uniform results)
    int tot = __reduce_add_sync(0xffffffffu, cnt);
    unsigned ovf = __ballot_sync(0xffffffffu, cnt > NCAND);

    unsigned long long key[KK];

    if (tot >= KK && ovf == 0u) {
        // Candidates provably contain the row top-8.
        #pragma unroll
        for (int i = 0; i < NCAND; i++) key[i] = cand[i];   // sorted desc already
        #pragma unroll
        for (int i = NCAND; i < KK; i++) key[i] = 0ull;
    } else {
        // Rare exact fallback: full per-lane scan of the row (L2-warm).
        #pragma unroll
        for (int i = 0; i < KK; i++) key[i] = 0ull;
        for (int j = lane; j < COLS / 4; j += 32) {
            float4 f = xr[j];
            int base = j * 4;
            insert8(key, pack_key(f.x, base + 0));
            insert8(key, pack_key(f.y, base + 1));
            insert8(key, pack_key(f.z, base + 2));
            insert8(key, pack_key(f.w, base + 3));
        }
    }

    // Warp bitonic merge: 32 lanes -> exact row top-8 on every lane
    #pragma unroll
    for (int d = 1; d < 32; d <<= 1)
        warp_merge_step(key, d);

    if (lane == 0)
        write_row_out<IDX_MODE>(d_out, row, key);
}

extern "C" void kernel_launch(void* const* d_in, const int* in_sizes, int n_in,
                              void* d_out, int out_size) {
    const float* x = (const float*)d_in[0];
    if (out_size == 2 * ROWS * KK) {
        topk8_warp_kernel<1><<<ROWS, 32>>>(x, d_out);
    } else {
        topk8_warp_kernel<0><<<ROWS, 32>>>(x, d_out);
    }
}

// round 16
// speedup vs baseline: 1.9192x; 1.9192x over previous
#include <cuda_runtime.h>
#include <cstdint>

#define ROWS 4096
#define COLS 8192
#define TPB  512
#define NW   (TPB / 32)    // 16 warps
#define RPC  2             // rows per CTA
#define NF4  4             // float4 per thread per row (8192/512/4)
#define KK   8
#define TH   2.75f
#define SCAP 512

// ---------- packed key helpers ----------

__device__ __forceinline__ unsigned long long pack_key(float v, int idx) {
    unsigned u = __float_as_uint(v);
    unsigned fk = (u & 0x80000000u) ? ~u : (u | 0x80000000u);
    return ((unsigned long long)fk << 32) | (unsigned)(~(unsigned)idx);
}

__device__ __forceinline__ void unpack_key(unsigned long long k, float& v, int& idx) {
    unsigned fk = (unsigned)(k >> 32);
    unsigned u  = (fk & 0x80000000u) ? (fk ^ 0x80000000u) : ~fk;
    v   = __uint_as_float(u);
    idx = (int)(~(unsigned)(k & 0xFFFFFFFFull));
}

// ---------- exact top-8 warp machinery (proven) ----------

__device__ __forceinline__ void cmpswap(unsigned long long& a, unsigned long long& b) {
    unsigned long long lo = a < b ? a : b;
    a = a > b ? a : b;
    b = lo;
}

__device__ __forceinline__ void bitonic_clean8(unsigned long long (&k)[KK]) {
    cmpswap(k[0], k[4]); cmpswap(k[1], k[5]); cmpswap(k[2], k[6]); cmpswap(k[3], k[7]);
    cmpswap(k[0], k[2]); cmpswap(k[1], k[3]); cmpswap(k[4], k[6]); cmpswap(k[5], k[7]);
    cmpswap(k[0], k[1]); cmpswap(k[2], k[3]); cmpswap(k[4], k[5]); cmpswap(k[6], k[7]);
}

__device__ __forceinline__ void warp_merge_step(unsigned long long (&k)[KK], int d) {
    unsigned long long o[KK];
    #pragma unroll
    for (int i = 0; i < KK; i++)
        o[i] = __shfl_xor_sync(0xffffffffu, k[KK - 1 - i], d);
    #pragma unroll
    for (int i = 0; i < KK; i++)
        k[i] = k[i] > o[i] ? k[i] : o[i];
    bitonic_clean8(k);
}

__device__ __forceinline__ void insert8(unsigned long long (&k)[KK], unsigned long long c) {
    if (c > k[KK - 1]) {
        k[KK - 1] = c;
        #pragma unroll
        for (int j = KK - 1; j > 0; --j) {
            if (k[j] > k[j - 1]) { unsigned long long t = k[j]; k[j] = k[j - 1]; k[j - 1] = t; }
        }
    }
}

// IDX_MODE: 1 = indices as float32 at element offset ROWS*KK (confirmed layout)
//           0 = indices as int64 at byte offset ROWS*KK*4 (fallback)
template <int IDX_MODE>
__device__ __forceinline__ void write_row_out(void* d_out, int row,
                                              const unsigned long long (&k)[KK]) {
    float* out_v = (float*)d_out;
    #pragma unroll
    for (int i = 0; i < KK; i++) {
        float val; int idx;
        unpack_key(k[i], val, idx);
        out_v[(size_t)row * KK + i] = val;
        if (IDX_MODE == 1) {
            float* out_i = out_v + (size_t)ROWS * KK;
            out_i[(size_t)row * KK + i] = (float)idx;
        } else {
            long long* out_i = (long long*)((char*)d_out + (size_t)ROWS * KK * sizeof(float));
            out_i[(size_t)row * KK + i] = (long long)idx;
        }
    }
}

// Warp-cooperative exact top-8 over a small candidate list; lanes stride list.
template <int IDX_MODE>
__device__ __forceinline__ void warp_epilogue(const unsigned long long* cand, int ncand,
                                              int lane, void* d_out, int row) {
    unsigned long long key[KK];
    #pragma unroll
    for (int i = 0; i < KK; i++) key[i] = 0ull;
    for (int j = lane; j < ncand; j += 32)
        insert8(key, cand[j]);
    #pragma unroll
    for (int d = 1; d < 32; d <<= 1)
        warp_merge_step(key, d);
    if (lane == 0)
        write_row_out<IDX_MODE>(d_out, row, key);
}

// ---------- kernel: 2 rows per CTA, front-batched loads, parallel epilogues ----------

template <int IDX_MODE>
__global__ __launch_bounds__(TPB, 2) void topk8_kernel(const float* __restrict__ x,
                                                       void* __restrict__ d_out) {
    const int row0 = blockIdx.x * RPC;
    const int t    = threadIdx.x;
    const int wid  = t >> 5;
    const int lane = t & 31;

    __shared__ unsigned long long s_cand[RPC][SCAP];
    __shared__ int s_nc[RPC];
    __shared__ unsigned long long s_top[NW][KK];

    if (t == 0) { s_nc[0] = 0; s_nc[1] = 0; }

    // ---- Phase 1: front-batch ALL loads for both rows (MLP = 8 per thread) ----
    const float4* xr0 = reinterpret_cast<const float4*>(x + (size_t)row0 * COLS);
    const float4* xr1 = reinterpret_cast<const float4*>(x + (size_t)(row0 + 1) * COLS);
    float4 v[RPC][NF4];
    #pragma unroll
    for (int i = 0; i < NF4; i++) v[0][i] = xr0[t + i * TPB];
    #pragma unroll
    for (int i = 0; i < NF4; i++) v[1][i] = xr1[t + i * TPB];

    __syncthreads();  // s_nc init visible before atomics

    // ---- Phase 2: filter both rows from registers into smem candidates ----
    #pragma unroll
    for (int r = 0; r < RPC; r++) {
        float m[NF4];
        #pragma unroll
        for (int i = 0; i < NF4; i++)
            m[i] = fmaxf(fmaxf(v[r][i].x, v[r][i].y), fmaxf(v[r][i].z, v[r][i].w));
        float mx = fmaxf(fmaxf(m[0], m[1]), fmaxf(m[2], m[3]));
        if (mx > TH) {
            #pragma unroll
            for (int i = 0; i < NF4; i++) {
                int base = (t + i * TPB) * 4;
                float f;
                f = v[r][i].x; if (f > TH) { int p = atomicAdd(&s_nc[r], 1); if (p < SCAP) s_cand[r][p] = pack_key(f, base + 0); }
                f = v[r][i].y; if (f > TH) { int p = atomicAdd(&s_nc[r], 1); if (p < SCAP) s_cand[r][p] = pack_key(f, base + 1); }
                f = v[r][i].z; if (f > TH) { int p = atomicAdd(&s_nc[r], 1); if (p < SCAP) s_cand[r][p] = pack_key(f, base + 2); }
                f = v[r][i].w; if (f > TH) { int p = atomicAdd(&s_nc[r], 1); if (p < SCAP) s_cand[r][p] = pack_key(f, base + 3); }
            }
        }
    }
    __syncthreads();

    const int nc0 = s_nc[0];
    const int nc1 = s_nc[1];
    const bool ok0 = (nc0 >= KK && nc0 <= SCAP);
    const bool ok1 = (nc1 >= KK && nc1 <= SCAP);

    if (ok0 && ok1) {
        // ---- Common path: two warps run the two row epilogues concurrently ----
        if (wid == 0)
            warp_epilogue<IDX_MODE>(s_cand[0], nc0, lane, d_out, row0);
        else if (wid == 1)
            warp_epilogue<IDX_MODE>(s_cand[1], nc1, lane, d_out, row0 + 1);
    } else {
        // ---- Rare path (CTA-uniform): handle each row, exact ----
        #pragma unroll
        for (int r = 0; r < RPC; r++) {
            const bool okr = (r == 0) ? ok0 : ok1;
            const int  ncr = (r == 0) ? nc0 : nc1;
            if (okr) {
                if (wid == 0)
                    warp_epilogue<IDX_MODE>(s_cand[r], ncr, lane, d_out, row0 + r);
            } else {
                // Full exact scan of row r from live registers, cross-warp merge.
                unsigned long long key[KK];
                #pragma unroll
                for (int i = 0; i < KK; i++) key[i] = 0ull;
                #pragma unroll
                for (int i = 0; i < NF4; i++) {
                    int base = (t + i * TPB) * 4;
                    insert8(key, pack_key(v[r][i].x, base + 0));
                    insert8(key, pack_key(v[r][i].y, base + 1));
                    insert8(key, pack_key(v[r][i].z, base + 2));
                    insert8(key, pack_key(v[r][i].w, base + 3));
                }
                #pragma unroll
                for (int d = 1; d < 32; d <<= 1)
                    warp_merge_step(key, d);
                if (lane == 0) {
                    #pragma unroll
                    for (int i = 0; i < KK; i++) s_top[wid][i] = key[i];
                }
                __syncthreads();  // uniform: whole CTA in this sub-branch for row r
                if (wid == 0) {
                    unsigned long long fk[KK];
                    #pragma unroll
                    for (int i = 0; i < KK; i++)
                        fk[i] = (lane < NW) ? s_top[lane][i] : 0ull;
                    warp_merge_step(fk, 1);
                    warp_merge_step(fk, 2);
                    warp_merge_step(fk, 4);
                    warp_merge_step(fk, 8);
                    if (lane == 0)
                        write_row_out<IDX_MODE>(d_out, row0 + r, fk);
                }
                __syncthreads();
            }
        }
    }
}

extern "C" void kernel_launch(void* const* d_in, const int* in_sizes, int n_in,
                              void* d_out, int out_size) {
    const float* x = (const float*)d_in[0];
    if (out_size == 2 * ROWS * KK) {
        topk8_kernel<1><<<ROWS / RPC, TPB>>>(x, d_out);
    } else {
        topk8_kernel<0><<<ROWS / RPC, TPB>>>(x, d_out);
    }
}